// round 11
// baseline (speedup 1.0000x reference)
#include <cuda_runtime.h>
#include <math.h>

// Problem constants
#define Bc   512
#define NAc  128
#define NLc  512
#define Dc   128
#define KAc  16
#define KLc  16
#define NNODES 32   // KA + KL

typedef unsigned long long u64;

// Scratch: computed node rows + selection.
__device__ float g_nodes[(size_t)Bc * NNODES * Dc];   // 8 MB
__device__ int   g_sel[Bc * NNODES];

// ---------------------------------------------------------------------------
// MLP dynamic shared layout (53376 bytes -> 4 blocks/SM)
//   Xs/Hs: float [128][36], transposed [k][row] (stride 36 floats = 144B)
//   Wst:   float [2][2048] double-buffered weight stage (8KB each)
// ---------------------------------------------------------------------------
#define SM_XS    0        // 18432
#define SM_HS    18432    // 18432
#define SM_WST   36864    // 16384
#define SM_SSEL  53248    // 128
#define SM_TOTAL 53376

// ---------------------------------------------------------------------------
// helpers
// ---------------------------------------------------------------------------
__device__ __forceinline__ u64 pk2(float lo, float hi) {
    u64 r;
    asm("mov.b64 %0, {%1, %2};" : "=l"(r) : "f"(lo), "f"(hi));
    return r;
}
__device__ __forceinline__ void fma2(u64& d, u64 a, u64 b) {
    asm("fma.rn.f32x2 %0, %1, %2, %0;" : "+l"(d) : "l"(a), "l"(b));
}
__device__ __forceinline__ void unpk2(u64 v, float& lo, float& hi) {
    asm("mov.b64 {%0, %1}, %2;" : "=f"(lo), "=f"(hi) : "l"(v));
}
__device__ __forceinline__ void cpa16(void* smem_dst, const void* gsrc) {
    unsigned sa = (unsigned)__cvta_generic_to_shared(smem_dst);
    asm volatile("cp.async.cg.shared.global [%0], [%1], 16;"
                 :: "r"(sa), "l"(gsrc));
}
#define CP_COMMIT() asm volatile("cp.async.commit_group;")
#define CP_WAIT0()  asm volatile("cp.async.wait_group 0;")

__device__ __forceinline__ float wsum32(float v) {
    #pragma unroll
    for (int o = 16; o > 0; o >>= 1) v += __shfl_xor_sync(0xffffffffu, v, o);
    return v;
}
__device__ __forceinline__ float gelu_exact(float x) {
    return 0.5f * x * (1.0f + erff(x * 0.70710678118654752440f));
}

// ---------------------------------------------------------------------------
// Kernel 1: selection (proven R2..R9). One block per batch.
// ---------------------------------------------------------------------------
__global__ void __launch_bounds__(128)
select_kernel(const float* __restrict__ lane_centers,
              const float* __restrict__ x_centers,
              const float* __restrict__ spike_rate,
              const void*  __restrict__ actor_valid_raw,
              const void*  __restrict__ lane_valid_raw)
{
    __shared__ float sv[NAc];
    __shared__ float ld[NLc];
    __shared__ int   sel[NNODES];
    __shared__ float ax[KAc], ay[KAc];

    const int tid = threadIdx.x;
    const int b   = blockIdx.x;

    // ---- Phase 0: detect boolean encoding (uint8 / int32 / float32) ----
    int enc;
    {
        const unsigned char* p =
            (const unsigned char*)lane_valid_raw + (size_t)b * 512;
        unsigned char b1 = p[tid * 4 + 1];
        unsigned char b2 = p[tid * 4 + 2];
        unsigned char b3 = p[tid * 4 + 3];
        int any1   = __syncthreads_or((int)b1);
        int anyOff = __syncthreads_or((int)(b1 | b2 | b3));
        enc = anyOff ? (any1 ? 0 : 2) : 1;
    }

    // ---- Phase A: actor top-16 (stable, jax top_k tie rule) ----
    {
        bool av;
        if (enc == 0)      av = ((const unsigned char*)actor_valid_raw)[(size_t)b * NAc + tid] != 0;
        else if (enc == 1) av = ((const int*)actor_valid_raw)[(size_t)b * NAc + tid] != 0;
        else               av = ((const float*)actor_valid_raw)[(size_t)b * NAc + tid] != 0.0f;
        float v = spike_rate[b * NAc + tid];
        sv[tid] = av ? v : -INFINITY;
    }
    __syncthreads();
    {
        float mv = sv[tid];
        int cnt = 0;
        #pragma unroll 8
        for (int j = 0; j < NAc; j++) {
            float o = sv[j];
            cnt += (o > mv) || (o == mv && j < tid);
        }
        if (cnt < KAc) sel[cnt] = tid;
    }
    __syncthreads();
    if (tid < KAc) {
        int a = sel[tid];
        ax[tid] = x_centers[((size_t)b * NAc + a) * 2 + 0];
        ay[tid] = x_centers[((size_t)b * NAc + a) * 2 + 1];
    }
    __syncthreads();

    // ---- Phase B: lane distances + top-16 smallest ----
    #pragma unroll
    for (int q = 0; q < 4; q++) {
        int l = tid + 128 * q;
        bool lv;
        if (enc == 0)      lv = ((const unsigned char*)lane_valid_raw)[(size_t)b * NLc + l] != 0;
        else if (enc == 1) lv = ((const int*)lane_valid_raw)[(size_t)b * NLc + l] != 0;
        else               lv = ((const float*)lane_valid_raw)[(size_t)b * NLc + l] != 0.0f;
        float d = INFINITY;
        if (lv) {
            float lx = lane_centers[((size_t)b * NLc + l) * 2 + 0];
            float ly = lane_centers[((size_t)b * NLc + l) * 2 + 1];
            float m2 = INFINITY;
            #pragma unroll
            for (int a = 0; a < KAc; a++) {
                float dx = __fadd_rn(ax[a], -lx);
                float dy = __fadd_rn(ay[a], -ly);
                float s = __fadd_rn(__fmul_rn(dx, dx), __fmul_rn(dy, dy));
                m2 = fminf(m2, s);
            }
            d = sqrtf(m2);   // sqrt monotone: min(sqrt(s)) == sqrt(min(s))
        }
        ld[l] = d;
    }
    __syncthreads();
    {
        float dl[4];
        int   cnt[4];
        #pragma unroll
        for (int q = 0; q < 4; q++) { dl[q] = ld[tid + 128 * q]; cnt[q] = 0; }
        #pragma unroll 4
        for (int j = 0; j < NLc; j++) {
            float o = ld[j];
            #pragma unroll
            for (int q = 0; q < 4; q++) {
                int l = tid + 128 * q;
                cnt[q] += (o < dl[q]) || (o == dl[q] && j < l);
            }
        }
        #pragma unroll
        for (int q = 0; q < 4; q++)
            if (cnt[q] < KLc) sel[KAc + cnt[q]] = tid + 128 * q;
    }
    __syncthreads();

    if (tid < NNODES) g_sel[b * NNODES + tid] = sel[tid];
}

// ---------------------------------------------------------------------------
// 32x128 @ 128x128 GEMM, 128 threads, cp.async double-buffered W.
// A: float [128][36] transposed [k][row]. Warp rg (tid>>5): rows 8rg..8rg+7
// (two broadcast LDS.128 -> four row-pair u64s). Lane cg (tid&31): cols
// 4cg..4cg+3 (one conflict-free LDS.128, 4 pk2 dups).
// Per kk: 3 LDS + 4 pk2 + 16 fma2  (0.375 wf/fma2 vs 0.625 in R9).
// ---------------------------------------------------------------------------
__device__ __forceinline__ void gemm_rc8(
    const float* A, const float* __restrict__ Wg,
    float* Wst, int tid, int rg, int cg, u64 (&acc)[4][4])
{
    #pragma unroll
    for (int rp = 0; rp < 4; rp++)
        #pragma unroll
        for (int c = 0; c < 4; c++) acc[rp][c] = 0ull;

    // prologue: stage 0 (16x128 fp32 = 8KB), 4x16B per thread
    #pragma unroll
    for (int i = 0; i < 4; i++)
        cpa16(Wst + (tid + 128 * i) * 4, Wg + (tid + 128 * i) * 4);
    CP_COMMIT();

    #pragma unroll 1
    for (int s = 0; s < 8; s++) {
        CP_WAIT0();          // stage-s copies landed
        __syncthreads();     // visible to all; prior stage reads complete
        if (s < 7) {
            float* dst = Wst + ((s + 1) & 1) * 2048;
            const float* src = Wg + (s + 1) * 2048;
            #pragma unroll
            for (int i = 0; i < 4; i++)
                cpa16(dst + (tid + 128 * i) * 4, src + (tid + 128 * i) * 4);
            CP_COMMIT();
        }
        const float* Ws = Wst + (s & 1) * 2048;
        const float* Ab = A + s * 16 * 36 + 8 * rg;
        #pragma unroll
        for (int kk = 0; kk < 16; kk++) {
            float4 w = *(const float4*)(Ws + kk * 128 + 4 * cg);
            u64 bx = pk2(w.x, w.x);
            u64 by = pk2(w.y, w.y);
            u64 bz = pk2(w.z, w.z);
            u64 bw = pk2(w.w, w.w);
            ulonglong2 a01 = *(const ulonglong2*)(Ab + kk * 36);      // rows 8rg..+3
            ulonglong2 a23 = *(const ulonglong2*)(Ab + kk * 36 + 4);  // rows 8rg+4..+7
            fma2(acc[0][0], a01.x, bx); fma2(acc[0][1], a01.x, by);
            fma2(acc[0][2], a01.x, bz); fma2(acc[0][3], a01.x, bw);
            fma2(acc[1][0], a01.y, bx); fma2(acc[1][1], a01.y, by);
            fma2(acc[1][2], a01.y, bz); fma2(acc[1][3], a01.y, bw);
            fma2(acc[2][0], a23.x, bx); fma2(acc[2][1], a23.x, by);
            fma2(acc[2][2], a23.x, bz); fma2(acc[2][3], a23.x, bw);
            fma2(acc[3][0], a23.y, bx); fma2(acc[3][1], a23.y, by);
            fma2(acc[3][2], a23.y, bz); fma2(acc[3][3], a23.y, bw);
        }
    }
}

// ---------------------------------------------------------------------------
// Kernel 2: MLP. One batch per block, 128 threads, 4 blocks/SM.
// ---------------------------------------------------------------------------
__global__ void __launch_bounds__(128, 4)
mlp_kernel(const float* __restrict__ actor_feat,
           const float* __restrict__ lane_feat,
           const float* __restrict__ W0a, const float* __restrict__ b0a,
           const float* __restrict__ W0b, const float* __restrict__ b0b,
           const float* __restrict__ W1a, const float* __restrict__ b1a,
           const float* __restrict__ W1b, const float* __restrict__ b1b,
           const float* __restrict__ gmm, const float* __restrict__ bta)
{
    extern __shared__ unsigned char smem_raw[];
    float* Xs  = (float*)(smem_raw + SM_XS);    // [k][row], stride 36
    float* Hs  = (float*)(smem_raw + SM_HS);
    float* Wst = (float*)(smem_raw + SM_WST);
    int*  ssel = (int*)(smem_raw + SM_SSEL);

    const int tid = threadIdx.x;
    const int b   = blockIdx.x;
    const int rg  = tid >> 5;    // warp -> rows 8rg..8rg+7
    const int cg  = tid & 31;    // lane -> cols 4cg..4cg+3

    if (tid < NNODES) ssel[tid] = g_sel[b * NNODES + tid];
    __syncthreads();

    // ---- gather: thread = feature column; 32 node rows ----
    #pragma unroll 4
    for (int rw = 0; rw < NNODES; rw++) {
        int idx = ssel[rw];
        const float* src = (rw < KAc)
            ? (actor_feat + ((size_t)b * NAc + idx) * Dc)
            : (lane_feat  + ((size_t)b * NLc + idx) * Dc);
        Xs[tid * 36 + rw] = src[tid];
    }
    // visibility to GEMM1 reads: behind gemm_rc8's stage-0 sync

    u64 acc[4][4];

    #pragma unroll 1
    for (int layer = 0; layer < 2; layer++) {
        const float* Wa  = layer ? W1a : W0a;
        const float* ba  = layer ? b1a : b0a;
        const float* Wb2 = layer ? W1b : W0b;
        const float* bb2 = layer ? b1b : b0b;

        // ---- GEMM1: H = gelu(X @ Wa + ba) -> Hs ----
        gemm_rc8(Xs, Wa, Wst, tid, rg, cg, acc);
        {
            float4 bq = *(const float4*)(ba + 4 * cg);
            float bar[4] = {bq.x, bq.y, bq.z, bq.w};
            #pragma unroll
            for (int rp = 0; rp < 4; rp++) {
                int r0 = 8 * rg + 2 * rp;
                #pragma unroll
                for (int c = 0; c < 4; c++) {
                    float lo, hi; unpk2(acc[rp][c], lo, hi);
                    lo = gelu_exact(lo + bar[c]);
                    hi = gelu_exact(hi + bar[c]);
                    *(float2*)(Hs + (4 * cg + c) * 36 + r0) = make_float2(lo, hi);
                }
            }
        }
        // Hs writes vs GEMM2 reads: behind gemm_rc8's stage-0 sync

        // ---- GEMM2: Y = H @ Wb + bb; Z = LN(X + Y) ----
        gemm_rc8(Hs, Wb2, Wst, tid, rg, cg, acc);
        {
            float4 bq = *(const float4*)(bb2 + 4 * cg);
            float bbr[4] = {bq.x, bq.y, bq.z, bq.w};
            float4 gq = *(const float4*)(gmm + 4 * cg);
            float4 pq = *(const float4*)(bta + 4 * cg);
            float gar[4] = {gq.x, gq.y, gq.z, gq.w};
            float per[4] = {pq.x, pq.y, pq.z, pq.w};

            #pragma unroll
            for (int rp = 0; rp < 4; rp++) {
                int r0 = 8 * rg + 2 * rp;
                float l0[4], l1[4];
                #pragma unroll
                for (int c = 0; c < 4; c++) {
                    float lo, hi; unpk2(acc[rp][c], lo, hi);
                    float2 xv = *(const float2*)(Xs + (4 * cg + c) * 36 + r0);
                    l0[c] = lo + bbr[c] + xv.x;
                    l1[c] = hi + bbr[c] + xv.y;
                }
                float m0 = wsum32(l0[0] + l0[1] + l0[2] + l0[3]) * 0.0078125f;
                float m1 = wsum32(l1[0] + l1[1] + l1[2] + l1[3]) * 0.0078125f;
                float q0 = 0.f, q1 = 0.f;
                #pragma unroll
                for (int c = 0; c < 4; c++) {
                    float d0 = l0[c] - m0; q0 += d0 * d0;
                    float d1 = l1[c] - m1; q1 += d1 * d1;
                }
                float i0 = rsqrtf(wsum32(q0) * 0.0078125f + 1e-5f);
                float i1 = rsqrtf(wsum32(q1) * 0.0078125f + 1e-5f);

                if (layer == 0) {
                    #pragma unroll
                    for (int c = 0; c < 4; c++) {
                        float z0 = (l0[c] - m0) * i0 * gar[c] + per[c];
                        float z1 = (l1[c] - m1) * i1 * gar[c] + per[c];
                        *(float2*)(Xs + (4 * cg + c) * 36 + r0) = make_float2(z0, z1);
                    }
                } else {
                    float4 o0, o1;
                    o0.x = (l0[0] - m0) * i0 * gar[0] + per[0];
                    o0.y = (l0[1] - m0) * i0 * gar[1] + per[1];
                    o0.z = (l0[2] - m0) * i0 * gar[2] + per[2];
                    o0.w = (l0[3] - m0) * i0 * gar[3] + per[3];
                    o1.x = (l1[0] - m1) * i1 * gar[0] + per[0];
                    o1.y = (l1[1] - m1) * i1 * gar[1] + per[1];
                    o1.z = (l1[2] - m1) * i1 * gar[2] + per[2];
                    o1.w = (l1[3] - m1) * i1 * gar[3] + per[3];
                    float* d0 = g_nodes + ((size_t)b * NNODES + r0) * Dc + 4 * cg;
                    *(float4*)d0        = o0;
                    *(float4*)(d0 + Dc) = o1;
                }
            }
        }
    }
}

// ---------------------------------------------------------------------------
// Scatter kernel: warp per row, float4 lanes (measured 7us).
// ---------------------------------------------------------------------------
__global__ void __launch_bounds__(256)
scatter_kernel(float* __restrict__ out)
{
    __shared__ int ssel[NNODES];
    const int tid = threadIdx.x;
    const int b   = blockIdx.x;
    if (tid < NNODES) ssel[tid] = g_sel[b * NNODES + tid];
    __syncthreads();
    const int w = tid >> 5, lane = tid & 31;
    const size_t lane_base = (size_t)Bc * NAc * Dc;
    #pragma unroll
    for (int it = 0; it < 4; it++) {
        int rr = it * 8 + w;
        int idx = ssel[rr];
        size_t base = (rr < KAc)
            ? ((size_t)b * NAc + idx) * Dc
            : lane_base + ((size_t)b * NLc + idx) * Dc;
        ((float4*)(out + base))[lane] =
            ((const float4*)(g_nodes + ((size_t)b * NNODES + rr) * Dc))[lane];
    }
}

__global__ void nop_kernel() {}

// ---------------------------------------------------------------------------
// kernel_launch: select -> nop,nop -> mlp -> CE memcpys -> scatter.
// Kernel order matches R9 (mlp is 4th kernel) so ncu captures mlp again.
// ---------------------------------------------------------------------------
extern "C" void kernel_launch(void* const* d_in, const int* in_sizes, int n_in,
                              void* d_out, int out_size)
{
    const float* actor_feat   = (const float*)d_in[0];
    const float* lane_feat    = (const float*)d_in[1];
    const float* lane_centers = (const float*)d_in[2];
    const float* x_centers    = (const float*)d_in[3];
    const float* spike_rate   = (const float*)d_in[4];
    const void*  actor_valid  = d_in[5];
    const void*  lane_valid   = d_in[6];
    const float* W0a = (const float*)d_in[7];
    const float* b0a = (const float*)d_in[8];
    const float* W0b = (const float*)d_in[9];
    const float* b0b = (const float*)d_in[10];
    const float* W1a = (const float*)d_in[11];
    const float* b1a = (const float*)d_in[12];
    const float* W1b = (const float*)d_in[13];
    const float* b1b = (const float*)d_in[14];
    const float* gmm = (const float*)d_in[15];
    const float* bta = (const float*)d_in[16];
    float* out = (float*)d_out;

    const size_t actor_elems = (size_t)Bc * NAc * Dc;
    const size_t lane_elems  = (size_t)Bc * NLc * Dc;

    cudaFuncSetAttribute(mlp_kernel,
                         cudaFuncAttributeMaxDynamicSharedMemorySize, SM_TOTAL);

    select_kernel<<<Bc, 128>>>(lane_centers, x_centers, spike_rate,
                               actor_valid, lane_valid);
    nop_kernel<<<1, 32>>>();
    nop_kernel<<<1, 32>>>();
    mlp_kernel<<<Bc, 128, SM_TOTAL>>>(actor_feat, lane_feat,
                                      W0a, b0a, W0b, b0b,
                                      W1a, b1a, W1b, b1b,
                                      gmm, bta);

    // Bulk pool copy into out (copy engine), then overwrite selected rows.
    cudaMemcpyAsync(out, actor_feat, actor_elems * sizeof(float),
                    cudaMemcpyDeviceToDevice, 0);
    cudaMemcpyAsync(out + actor_elems, lane_feat, lane_elems * sizeof(float),
                    cudaMemcpyDeviceToDevice, 0);

    scatter_kernel<<<Bc, 256>>>(out);
}

// round 12
// speedup vs baseline: 1.1646x; 1.1646x over previous
#include <cuda_runtime.h>
#include <math.h>

// Problem constants
#define Bc   512
#define NAc  128
#define NLc  512
#define Dc   128
#define KAc  16
#define KLc  16
#define NNODES 32   // KA + KL

typedef unsigned long long u64;

// ---------------------------------------------------------------------------
// Fused-kernel dynamic shared layout (53376 bytes -> 4 blocks/SM)
//   Xs/Hs: float [128][36], transposed [k][row] (stride 36 floats = 144B)
//   Wst:   float [2][2048] double-buffered weight stage (8KB each)
//   During the select phase: ld[512] overlays Wst; sv/ax/ay overlay Hs.
// ---------------------------------------------------------------------------
#define SM_XS    0        // 18432
#define SM_HS    18432    // 18432
#define SM_WST   36864    // 16384
#define SM_SSEL  53248    // 128 (int[32])
#define SM_TOTAL 53376

// ---------------------------------------------------------------------------
// helpers
// ---------------------------------------------------------------------------
__device__ __forceinline__ u64 pk2(float lo, float hi) {
    u64 r;
    asm("mov.b64 %0, {%1, %2};" : "=l"(r) : "f"(lo), "f"(hi));
    return r;
}
__device__ __forceinline__ void fma2(u64& d, u64 a, u64 b) {
    asm("fma.rn.f32x2 %0, %1, %2, %0;" : "+l"(d) : "l"(a), "l"(b));
}
__device__ __forceinline__ void unpk2(u64 v, float& lo, float& hi) {
    asm("mov.b64 {%0, %1}, %2;" : "=f"(lo), "=f"(hi) : "l"(v));
}
__device__ __forceinline__ void cpa16(void* smem_dst, const void* gsrc) {
    unsigned sa = (unsigned)__cvta_generic_to_shared(smem_dst);
    asm volatile("cp.async.cg.shared.global [%0], [%1], 16;"
                 :: "r"(sa), "l"(gsrc));
}
#define CP_COMMIT() asm volatile("cp.async.commit_group;")
#define CP_WAIT0()  asm volatile("cp.async.wait_group 0;")

__device__ __forceinline__ float wsum32(float v) {
    #pragma unroll
    for (int o = 16; o > 0; o >>= 1) v += __shfl_xor_sync(0xffffffffu, v, o);
    return v;
}
__device__ __forceinline__ float gelu_exact(float x) {
    return 0.5f * x * (1.0f + erff(x * 0.70710678118654752440f));
}

// ---------------------------------------------------------------------------
// 32x128 @ 128x128 GEMM, 128 threads, cp.async double-buffered W staging and
// manually software-pipelined inner loads (kk+1 operands fetched during kk).
// A: float [128][36] transposed [k][row]. Warp rg: rows 8rg..8rg+7.
// Lane cg: cols 4cg..4cg+3. Per kk: 3 LDS + 4 pk2 + 16 fma2.
// ---------------------------------------------------------------------------
__device__ __forceinline__ void gemm_rc8(
    const float* A, const float* __restrict__ Wg,
    float* Wst, int tid, int rg, int cg, u64 (&acc)[4][4])
{
    #pragma unroll
    for (int rp = 0; rp < 4; rp++)
        #pragma unroll
        for (int c = 0; c < 4; c++) acc[rp][c] = 0ull;

    // prologue: stage 0 (16x128 fp32 = 8KB), 4x16B per thread
    #pragma unroll
    for (int i = 0; i < 4; i++)
        cpa16(Wst + (tid + 128 * i) * 4, Wg + (tid + 128 * i) * 4);
    CP_COMMIT();

    #pragma unroll 1
    for (int s = 0; s < 8; s++) {
        CP_WAIT0();          // stage-s copies landed
        __syncthreads();     // visible to all; prior stage reads complete
        if (s < 7) {
            float* dst = Wst + ((s + 1) & 1) * 2048;
            const float* src = Wg + (s + 1) * 2048;
            #pragma unroll
            for (int i = 0; i < 4; i++)
                cpa16(dst + (tid + 128 * i) * 4, src + (tid + 128 * i) * 4);
            CP_COMMIT();
        }
        const float* Ws = Wst + (s & 1) * 2048;
        const float* Ab = A + s * 16 * 36 + 8 * rg;

        // preload kk = 0 operands
        float4 w        = *(const float4*)(Ws + 4 * cg);
        ulonglong2 a01  = *(const ulonglong2*)(Ab);
        ulonglong2 a23  = *(const ulonglong2*)(Ab + 4);

        #pragma unroll
        for (int kk = 0; kk < 16; kk++) {
            float4 wn; ulonglong2 a01n, a23n;
            if (kk < 15) {   // fetch next iteration's operands now
                wn   = *(const float4*)(Ws + (kk + 1) * 128 + 4 * cg);
                a01n = *(const ulonglong2*)(Ab + (kk + 1) * 36);
                a23n = *(const ulonglong2*)(Ab + (kk + 1) * 36 + 4);
            }
            u64 bx = pk2(w.x, w.x);
            u64 by = pk2(w.y, w.y);
            u64 bz = pk2(w.z, w.z);
            u64 bw = pk2(w.w, w.w);
            fma2(acc[0][0], a01.x, bx); fma2(acc[0][1], a01.x, by);
            fma2(acc[0][2], a01.x, bz); fma2(acc[0][3], a01.x, bw);
            fma2(acc[1][0], a01.y, bx); fma2(acc[1][1], a01.y, by);
            fma2(acc[1][2], a01.y, bz); fma2(acc[1][3], a01.y, bw);
            fma2(acc[2][0], a23.x, bx); fma2(acc[2][1], a23.x, by);
            fma2(acc[2][2], a23.x, bz); fma2(acc[2][3], a23.x, bw);
            fma2(acc[3][0], a23.y, bx); fma2(acc[3][1], a23.y, by);
            fma2(acc[3][2], a23.y, bz); fma2(acc[3][3], a23.y, bw);
            if (kk < 15) { w = wn; a01 = a01n; a23 = a23n; }
        }
    }
}

// ---------------------------------------------------------------------------
// Fused kernel: selection -> gather -> 2x(MLP+LN) -> direct scatter into out.
// Runs AFTER the bulk pool memcpys, so it can overwrite selected rows in out.
// ---------------------------------------------------------------------------
__global__ void __launch_bounds__(128, 4)
fused_kernel(const float* __restrict__ actor_feat,
             const float* __restrict__ lane_feat,
             const float* __restrict__ lane_centers,
             const float* __restrict__ x_centers,
             const float* __restrict__ spike_rate,
             const void*  __restrict__ actor_valid_raw,
             const void*  __restrict__ lane_valid_raw,
             const float* __restrict__ W0a, const float* __restrict__ b0a,
             const float* __restrict__ W0b, const float* __restrict__ b0b,
             const float* __restrict__ W1a, const float* __restrict__ b1a,
             const float* __restrict__ W1b, const float* __restrict__ b1b,
             const float* __restrict__ gmm, const float* __restrict__ bta,
             float* __restrict__ out)
{
    extern __shared__ unsigned char smem_raw[];
    float* Xs  = (float*)(smem_raw + SM_XS);    // [k][row], stride 36
    float* Hs  = (float*)(smem_raw + SM_HS);
    float* Wst = (float*)(smem_raw + SM_WST);
    int*  ssel = (int*)(smem_raw + SM_SSEL);
    // select-phase overlays (dead once GEMMs start)
    float* sv  = (float*)(smem_raw + SM_HS);          // [128]
    float* ax  = (float*)(smem_raw + SM_HS) + 128;    // [16]
    float* ay  = (float*)(smem_raw + SM_HS) + 144;    // [16]
    float* ld  = (float*)(smem_raw + SM_WST);         // [512]

    const int tid = threadIdx.x;
    const int b   = blockIdx.x;
    const int rg  = tid >> 5;    // warp -> rows 8rg..8rg+7
    const int cg  = tid & 31;    // lane -> cols 4cg..4cg+3

    // ============ Phase 0: detect boolean encoding (u8 / i32 / f32) ========
    int enc;
    {
        const unsigned char* p =
            (const unsigned char*)lane_valid_raw + (size_t)b * 512;
        unsigned char b1 = p[tid * 4 + 1];
        unsigned char b2 = p[tid * 4 + 2];
        unsigned char b3 = p[tid * 4 + 3];
        int any1   = __syncthreads_or((int)b1);
        int anyOff = __syncthreads_or((int)(b1 | b2 | b3));
        enc = anyOff ? (any1 ? 0 : 2) : 1;
    }

    // ============ Phase A: actor top-16 (stable, jax tie rule) =============
    {
        bool av;
        if (enc == 0)      av = ((const unsigned char*)actor_valid_raw)[(size_t)b * NAc + tid] != 0;
        else if (enc == 1) av = ((const int*)actor_valid_raw)[(size_t)b * NAc + tid] != 0;
        else               av = ((const float*)actor_valid_raw)[(size_t)b * NAc + tid] != 0.0f;
        float v = spike_rate[b * NAc + tid];
        sv[tid] = av ? v : -INFINITY;
    }
    __syncthreads();
    {
        float mv = sv[tid];
        int cnt = 0;
        #pragma unroll 8
        for (int j = 0; j < NAc; j++) {
            float o = sv[j];
            cnt += (o > mv) || (o == mv && j < tid);
        }
        if (cnt < KAc) ssel[cnt] = tid;
    }
    __syncthreads();
    if (tid < KAc) {
        int a = ssel[tid];
        ax[tid] = x_centers[((size_t)b * NAc + a) * 2 + 0];
        ay[tid] = x_centers[((size_t)b * NAc + a) * 2 + 1];
    }
    __syncthreads();

    // ============ Phase B: lane distances + top-16 smallest ================
    #pragma unroll
    for (int q = 0; q < 4; q++) {
        int l = tid + 128 * q;
        bool lv;
        if (enc == 0)      lv = ((const unsigned char*)lane_valid_raw)[(size_t)b * NLc + l] != 0;
        else if (enc == 1) lv = ((const int*)lane_valid_raw)[(size_t)b * NLc + l] != 0;
        else               lv = ((const float*)lane_valid_raw)[(size_t)b * NLc + l] != 0.0f;
        float d = INFINITY;
        if (lv) {
            float lx = lane_centers[((size_t)b * NLc + l) * 2 + 0];
            float ly = lane_centers[((size_t)b * NLc + l) * 2 + 1];
            float m2 = INFINITY;
            #pragma unroll
            for (int a = 0; a < KAc; a++) {
                float dx = __fadd_rn(ax[a], -lx);
                float dy = __fadd_rn(ay[a], -ly);
                float s = __fadd_rn(__fmul_rn(dx, dx), __fmul_rn(dy, dy));
                m2 = fminf(m2, s);
            }
            d = sqrtf(m2);   // sqrt monotone: min(sqrt(s)) == sqrt(min(s))
        }
        ld[l] = d;
    }
    __syncthreads();
    {
        float dl[4];
        int   cnt[4];
        #pragma unroll
        for (int q = 0; q < 4; q++) { dl[q] = ld[tid + 128 * q]; cnt[q] = 0; }
        #pragma unroll 4
        for (int j = 0; j < NLc; j++) {
            float o = ld[j];
            #pragma unroll
            for (int q = 0; q < 4; q++) {
                int l = tid + 128 * q;
                cnt[q] += (o < dl[q]) || (o == dl[q] && j < l);
            }
        }
        #pragma unroll
        for (int q = 0; q < 4; q++)
            if (cnt[q] < KLc) ssel[KAc + cnt[q]] = tid + 128 * q;
    }
    __syncthreads();   // ssel complete; select overlays dead below

    // ============ Phase C: gather nodes (transposed into Xs) ===============
    #pragma unroll 4
    for (int rw = 0; rw < NNODES; rw++) {
        int idx = ssel[rw];
        const float* src = (rw < KAc)
            ? (actor_feat + ((size_t)b * NAc + idx) * Dc)
            : (lane_feat  + ((size_t)b * NLc + idx) * Dc);
        Xs[tid * 36 + rw] = src[tid];
    }
    // visibility to GEMM1 reads: behind gemm_rc8's stage-0 sync

    // ============ Phase D: 2 layers of residual MLP + LayerNorm ============
    u64 acc[4][4];
    const size_t lane_base = (size_t)Bc * NAc * Dc;

    #pragma unroll 1
    for (int layer = 0; layer < 2; layer++) {
        const float* Wa  = layer ? W1a : W0a;
        const float* ba  = layer ? b1a : b0a;
        const float* Wb2 = layer ? W1b : W0b;
        const float* bb2 = layer ? b1b : b0b;

        // ---- GEMM1: H = gelu(X @ Wa + ba) -> Hs ----
        gemm_rc8(Xs, Wa, Wst, tid, rg, cg, acc);
        {
            float4 bq = *(const float4*)(ba + 4 * cg);
            float bar[4] = {bq.x, bq.y, bq.z, bq.w};
            #pragma unroll
            for (int rp = 0; rp < 4; rp++) {
                int r0 = 8 * rg + 2 * rp;
                #pragma unroll
                for (int c = 0; c < 4; c++) {
                    float lo, hi; unpk2(acc[rp][c], lo, hi);
                    lo = gelu_exact(lo + bar[c]);
                    hi = gelu_exact(hi + bar[c]);
                    *(float2*)(Hs + (4 * cg + c) * 36 + r0) = make_float2(lo, hi);
                }
            }
        }
        // Hs writes vs GEMM2 reads: behind gemm_rc8's stage-0 sync

        // ---- GEMM2: Y = H @ Wb + bb; Z = LN(X + Y) ----
        gemm_rc8(Hs, Wb2, Wst, tid, rg, cg, acc);
        {
            float4 bq = *(const float4*)(bb2 + 4 * cg);
            float bbr[4] = {bq.x, bq.y, bq.z, bq.w};
            float4 gq = *(const float4*)(gmm + 4 * cg);
            float4 pq = *(const float4*)(bta + 4 * cg);
            float gar[4] = {gq.x, gq.y, gq.z, gq.w};
            float per[4] = {pq.x, pq.y, pq.z, pq.w};

            #pragma unroll
            for (int rp = 0; rp < 4; rp++) {
                int r0 = 8 * rg + 2 * rp;
                float l0[4], l1[4];
                #pragma unroll
                for (int c = 0; c < 4; c++) {
                    float lo, hi; unpk2(acc[rp][c], lo, hi);
                    float2 xv = *(const float2*)(Xs + (4 * cg + c) * 36 + r0);
                    l0[c] = lo + bbr[c] + xv.x;
                    l1[c] = hi + bbr[c] + xv.y;
                }
                float m0 = wsum32(l0[0] + l0[1] + l0[2] + l0[3]) * 0.0078125f;
                float m1 = wsum32(l1[0] + l1[1] + l1[2] + l1[3]) * 0.0078125f;
                float q0 = 0.f, q1 = 0.f;
                #pragma unroll
                for (int c = 0; c < 4; c++) {
                    float d0 = l0[c] - m0; q0 += d0 * d0;
                    float d1 = l1[c] - m1; q1 += d1 * d1;
                }
                float i0 = rsqrtf(wsum32(q0) * 0.0078125f + 1e-5f);
                float i1 = rsqrtf(wsum32(q1) * 0.0078125f + 1e-5f);

                if (layer == 0) {
                    #pragma unroll
                    for (int c = 0; c < 4; c++) {
                        float z0 = (l0[c] - m0) * i0 * gar[c] + per[c];
                        float z1 = (l1[c] - m1) * i1 * gar[c] + per[c];
                        *(float2*)(Xs + (4 * cg + c) * 36 + r0) = make_float2(z0, z1);
                    }
                } else {
                    // ---- direct scatter into out (pool copy already done) --
                    float4 o0, o1;
                    o0.x = (l0[0] - m0) * i0 * gar[0] + per[0];
                    o0.y = (l0[1] - m0) * i0 * gar[1] + per[1];
                    o0.z = (l0[2] - m0) * i0 * gar[2] + per[2];
                    o0.w = (l0[3] - m0) * i0 * gar[3] + per[3];
                    o1.x = (l1[0] - m1) * i1 * gar[0] + per[0];
                    o1.y = (l1[1] - m1) * i1 * gar[1] + per[1];
                    o1.z = (l1[2] - m1) * i1 * gar[2] + per[2];
                    o1.w = (l1[3] - m1) * i1 * gar[3] + per[3];
                    int idx0 = ssel[r0];
                    int idx1 = ssel[r0 + 1];
                    float* d0 = (r0 < KAc)
                        ? out + ((size_t)b * NAc + idx0) * Dc
                        : out + lane_base + ((size_t)b * NLc + idx0) * Dc;
                    float* d1 = (r0 + 1 < KAc)
                        ? out + ((size_t)b * NAc + idx1) * Dc
                        : out + lane_base + ((size_t)b * NLc + idx1) * Dc;
                    *(float4*)(d0 + 4 * cg) = o0;
                    *(float4*)(d1 + 4 * cg) = o1;
                }
            }
        }
    }
}

// ---------------------------------------------------------------------------
// kernel_launch: memcpyA, memcpyL (CE), then ONE fused kernel. 3 graph nodes.
// ---------------------------------------------------------------------------
extern "C" void kernel_launch(void* const* d_in, const int* in_sizes, int n_in,
                              void* d_out, int out_size)
{
    const float* actor_feat   = (const float*)d_in[0];
    const float* lane_feat    = (const float*)d_in[1];
    const float* lane_centers = (const float*)d_in[2];
    const float* x_centers    = (const float*)d_in[3];
    const float* spike_rate   = (const float*)d_in[4];
    const void*  actor_valid  = d_in[5];
    const void*  lane_valid   = d_in[6];
    const float* W0a = (const float*)d_in[7];
    const float* b0a = (const float*)d_in[8];
    const float* W0b = (const float*)d_in[9];
    const float* b0b = (const float*)d_in[10];
    const float* W1a = (const float*)d_in[11];
    const float* b1a = (const float*)d_in[12];
    const float* W1b = (const float*)d_in[13];
    const float* b1b = (const float*)d_in[14];
    const float* gmm = (const float*)d_in[15];
    const float* bta = (const float*)d_in[16];
    float* out = (float*)d_out;

    const size_t actor_elems = (size_t)Bc * NAc * Dc;
    const size_t lane_elems  = (size_t)Bc * NLc * Dc;

    cudaFuncSetAttribute(fused_kernel,
                         cudaFuncAttributeMaxDynamicSharedMemorySize, SM_TOTAL);

    // Bulk pool copy into out (copy engine) FIRST.
    cudaMemcpyAsync(out, actor_feat, actor_elems * sizeof(float),
                    cudaMemcpyDeviceToDevice, 0);
    cudaMemcpyAsync(out + actor_elems, lane_feat, lane_elems * sizeof(float),
                    cudaMemcpyDeviceToDevice, 0);

    // One fused kernel: select + MLP + direct scatter into out.
    fused_kernel<<<Bc, 128, SM_TOTAL>>>(actor_feat, lane_feat, lane_centers,
                                        x_centers, spike_rate, actor_valid,
                                        lane_valid,
                                        W0a, b0a, W0b, b0b,
                                        W1a, b1a, W1b, b1b,
                                        gmm, bta, out);
}

// round 13
// speedup vs baseline: 1.6023x; 1.3758x over previous
#include <cuda_runtime.h>
#include <math.h>

// Problem constants
#define Bc   512
#define NAc  128
#define NLc  512
#define Dc   128
#define KAc  16
#define KLc  16
#define NNODES 32   // KA + KL

typedef unsigned long long u64;
typedef unsigned int u32;
#define KMAX 0xFFFFFFFFFFFFFFFFull

// Scratch: computed node rows + selection (consumed by scatter kernel).
__device__ float g_nodes[(size_t)Bc * NNODES * Dc];   // 8 MB
__device__ int   g_sel[Bc * NNODES];

// ---------------------------------------------------------------------------
// Dynamic shared layout (53376 bytes -> up to 4 blocks/SM)
//   Xs/Hs: float [128][36], transposed [k][row] (stride 36 floats = 144B)
//   Wst:   float [2][2048] double-buffered weight stage
//   Select-phase overlays on Hs: keysA[128] u64, cand[64] u64, ax/ay[16]
// ---------------------------------------------------------------------------
#define SM_XS    0        // 18432
#define SM_HS    18432    // 18432
#define SM_WST   36864    // 16384
#define SM_SSEL  53248    // 128 (int[32])
#define SM_TOTAL 53376

// ---------------------------------------------------------------------------
// helpers
// ---------------------------------------------------------------------------
__device__ __forceinline__ u64 pk2(float lo, float hi) {
    u64 r;
    asm("mov.b64 %0, {%1, %2};" : "=l"(r) : "f"(lo), "f"(hi));
    return r;
}
__device__ __forceinline__ void fma2(u64& d, u64 a, u64 b) {
    asm("fma.rn.f32x2 %0, %1, %2, %0;" : "+l"(d) : "l"(a), "l"(b));
}
__device__ __forceinline__ void unpk2(u64 v, float& lo, float& hi) {
    asm("mov.b64 {%0, %1}, %2;" : "=f"(lo), "=f"(hi) : "l"(v));
}
__device__ __forceinline__ void cpa16(void* smem_dst, const void* gsrc) {
    unsigned sa = (unsigned)__cvta_generic_to_shared(smem_dst);
    asm volatile("cp.async.cg.shared.global [%0], [%1], 16;"
                 :: "r"(sa), "l"(gsrc));
}
#define CP_COMMIT() asm volatile("cp.async.commit_group;")
#define CP_WAIT0()  asm volatile("cp.async.wait_group 0;")

__device__ __forceinline__ float wsum32(float v) {
    #pragma unroll
    for (int o = 16; o > 0; o >>= 1) v += __shfl_xor_sync(0xffffffffu, v, o);
    return v;
}
__device__ __forceinline__ float gelu_exact(float x) {
    return 0.5f * x * (1.0f + erff(x * 0.70710678118654752440f));
}
// monotone float->uint map: f1 < f2  <=>  fmono(f1) < fmono(f2)  (incl. +-inf)
__device__ __forceinline__ u32 fmono(float f) {
    u32 u = __float_as_uint(f);
    return (u & 0x80000000u) ? ~u : (u | 0x80000000u);
}
__device__ __forceinline__ u64 umin64(u64 a, u64 b) { return a < b ? a : b; }

// Warp-collective: extract the 16 smallest of the 128 keys held as k[0..3]
// per lane (all keys unique). Emits them in ascending order via emit(r, key).
template <typename EMIT>
__device__ __forceinline__ void warp_top16(u64 (&k)[4], EMIT emit, int lane) {
    #pragma unroll 1
    for (int r = 0; r < 16; r++) {
        u64 lm = umin64(umin64(k[0], k[1]), umin64(k[2], k[3]));
        #pragma unroll
        for (int o = 16; o > 0; o >>= 1)
            lm = umin64(lm, __shfl_xor_sync(0xffffffffu, lm, o));
        // lm == global min; unique owner invalidates its copy
        if      (k[0] == lm) k[0] = KMAX;
        else if (k[1] == lm) k[1] = KMAX;
        else if (k[2] == lm) k[2] = KMAX;
        else if (k[3] == lm) k[3] = KMAX;
        if (lane == 0) emit(r, lm);
    }
}

// ---------------------------------------------------------------------------
// 32x128 @ 128x128 GEMM, 128 threads, cp.async double-buffered W staging,
// software-pipelined inner loads (kk+1 operands fetched during kk).
// ---------------------------------------------------------------------------
__device__ __forceinline__ void gemm_rc8(
    const float* A, const float* __restrict__ Wg,
    float* Wst, int tid, int rg, int cg, u64 (&acc)[4][4])
{
    #pragma unroll
    for (int rp = 0; rp < 4; rp++)
        #pragma unroll
        for (int c = 0; c < 4; c++) acc[rp][c] = 0ull;

    #pragma unroll
    for (int i = 0; i < 4; i++)
        cpa16(Wst + (tid + 128 * i) * 4, Wg + (tid + 128 * i) * 4);
    CP_COMMIT();

    #pragma unroll 1
    for (int s = 0; s < 8; s++) {
        CP_WAIT0();
        __syncthreads();
        if (s < 7) {
            float* dst = Wst + ((s + 1) & 1) * 2048;
            const float* src = Wg + (s + 1) * 2048;
            #pragma unroll
            for (int i = 0; i < 4; i++)
                cpa16(dst + (tid + 128 * i) * 4, src + (tid + 128 * i) * 4);
            CP_COMMIT();
        }
        const float* Ws = Wst + (s & 1) * 2048;
        const float* Ab = A + s * 16 * 36 + 8 * rg;

        float4 w        = *(const float4*)(Ws + 4 * cg);
        ulonglong2 a01  = *(const ulonglong2*)(Ab);
        ulonglong2 a23  = *(const ulonglong2*)(Ab + 4);

        #pragma unroll
        for (int kk = 0; kk < 16; kk++) {
            float4 wn; ulonglong2 a01n, a23n;
            if (kk < 15) {
                wn   = *(const float4*)(Ws + (kk + 1) * 128 + 4 * cg);
                a01n = *(const ulonglong2*)(Ab + (kk + 1) * 36);
                a23n = *(const ulonglong2*)(Ab + (kk + 1) * 36 + 4);
            }
            u64 bx = pk2(w.x, w.x);
            u64 by = pk2(w.y, w.y);
            u64 bz = pk2(w.z, w.z);
            u64 bw = pk2(w.w, w.w);
            fma2(acc[0][0], a01.x, bx); fma2(acc[0][1], a01.x, by);
            fma2(acc[0][2], a01.x, bz); fma2(acc[0][3], a01.x, bw);
            fma2(acc[1][0], a01.y, bx); fma2(acc[1][1], a01.y, by);
            fma2(acc[1][2], a01.y, bz); fma2(acc[1][3], a01.y, bw);
            fma2(acc[2][0], a23.x, bx); fma2(acc[2][1], a23.x, by);
            fma2(acc[2][2], a23.x, bz); fma2(acc[2][3], a23.x, bw);
            fma2(acc[3][0], a23.y, bx); fma2(acc[3][1], a23.y, by);
            fma2(acc[3][2], a23.y, bz); fma2(acc[3][3], a23.y, bw);
            if (kk < 15) { w = wn; a01 = a01n; a23 = a23n; }
        }
    }
}

// ---------------------------------------------------------------------------
// Fused compute: tournament selection -> gather -> 2x(MLP+LN) -> g_nodes
// ---------------------------------------------------------------------------
__global__ void __launch_bounds__(128, 4)
compute_kernel(const float* __restrict__ actor_feat,
               const float* __restrict__ lane_feat,
               const float* __restrict__ lane_centers,
               const float* __restrict__ x_centers,
               const float* __restrict__ spike_rate,
               const void*  __restrict__ actor_valid_raw,
               const void*  __restrict__ lane_valid_raw,
               const float* __restrict__ W0a, const float* __restrict__ b0a,
               const float* __restrict__ W0b, const float* __restrict__ b0b,
               const float* __restrict__ W1a, const float* __restrict__ b1a,
               const float* __restrict__ W1b, const float* __restrict__ b1b,
               const float* __restrict__ gmm, const float* __restrict__ bta)
{
    extern __shared__ unsigned char smem_raw[];
    float* Xs  = (float*)(smem_raw + SM_XS);    // [k][row], stride 36
    float* Hs  = (float*)(smem_raw + SM_HS);
    float* Wst = (float*)(smem_raw + SM_WST);
    int*  ssel = (int*)(smem_raw + SM_SSEL);
    // select-phase overlays on Hs (dead once GEMMs start)
    u64*   keysA = (u64*)(smem_raw + SM_HS);            // [128]
    u64*   cand  = (u64*)(smem_raw + SM_HS + 1024);     // [64]
    float* ax    = (float*)(smem_raw + SM_HS + 1536);   // [16]
    float* ay    = (float*)(smem_raw + SM_HS + 1600);   // [16]

    const int tid  = threadIdx.x;
    const int b    = blockIdx.x;
    const int wid  = tid >> 5;
    const int lane = tid & 31;
    const int rg   = wid;        // warp -> rows 8rg..8rg+7 (GEMM)
    const int cg   = lane;       // lane -> cols 4cg..4cg+3 (GEMM)

    // ============ Phase 0: detect boolean encoding (u8 / i32 / f32) ========
    int enc;
    {
        const unsigned char* p =
            (const unsigned char*)lane_valid_raw + (size_t)b * 512;
        unsigned char b1 = p[tid * 4 + 1];
        unsigned char b2 = p[tid * 4 + 2];
        unsigned char b3 = p[tid * 4 + 3];
        int any1   = __syncthreads_or((int)b1);
        int anyOff = __syncthreads_or((int)(b1 | b2 | b3));
        enc = anyOff ? (any1 ? 0 : 2) : 1;
    }

    // ============ Phase A: actor top-16 (tournament, jax tie rule) =========
    {
        bool av;
        if (enc == 0)      av = ((const unsigned char*)actor_valid_raw)[(size_t)b * NAc + tid] != 0;
        else if (enc == 1) av = ((const int*)actor_valid_raw)[(size_t)b * NAc + tid] != 0;
        else               av = ((const float*)actor_valid_raw)[(size_t)b * NAc + tid] != 0.0f;
        float v = av ? spike_rate[b * NAc + tid] : -INFINITY;
        // descending-value key: ~fmono(v), tie -> lower index first
        keysA[tid] = ((u64)(~fmono(v)) << 32) | (u32)tid;
    }
    __syncthreads();
    if (wid == 0) {
        u64 k[4] = { keysA[lane], keysA[lane + 32],
                     keysA[lane + 64], keysA[lane + 96] };
        warp_top16(k, [&](int r, u64 gm) {
            ssel[r] = (int)(gm & 0xFFFFFFFFull);
        }, lane);
    }
    __syncthreads();
    if (tid < KAc) {
        int a = ssel[tid];
        ax[tid] = x_centers[((size_t)b * NAc + a) * 2 + 0];
        ay[tid] = x_centers[((size_t)b * NAc + a) * 2 + 1];
    }
    __syncthreads();

    // ============ Phase B: lane distances + top-16 (tournament) ============
    {
        u64 k[4];
        #pragma unroll
        for (int q = 0; q < 4; q++) {
            int l = 128 * wid + lane + 32 * q;   // this warp owns lanes [128w,128w+128)
            bool lv;
            if (enc == 0)      lv = ((const unsigned char*)lane_valid_raw)[(size_t)b * NLc + l] != 0;
            else if (enc == 1) lv = ((const int*)lane_valid_raw)[(size_t)b * NLc + l] != 0;
            else               lv = ((const float*)lane_valid_raw)[(size_t)b * NLc + l] != 0.0f;
            float d = INFINITY;
            if (lv) {
                float lx = lane_centers[((size_t)b * NLc + l) * 2 + 0];
                float ly = lane_centers[((size_t)b * NLc + l) * 2 + 1];
                float m2 = INFINITY;
                #pragma unroll
                for (int a = 0; a < KAc; a++) {
                    float dx = __fadd_rn(ax[a], -lx);
                    float dy = __fadd_rn(ay[a], -ly);
                    float s = __fadd_rn(__fmul_rn(dx, dx), __fmul_rn(dy, dy));
                    m2 = fminf(m2, s);
                }
                d = sqrtf(m2);   // sqrt monotone: min(sqrt) == sqrt(min)
            }
            // ascending-distance key, tie -> lower index first
            k[q] = ((u64)fmono(d) << 32) | (u32)l;
        }
        warp_top16(k, [&](int r, u64 gm) {
            cand[wid * 16 + r] = gm;
        }, lane);
    }
    __syncthreads();
    // merge 4x16 candidates: exact rank by unique-key count (no ties possible)
    if (tid < 64) {
        u64 mk = cand[tid];
        int cnt = 0;
        #pragma unroll 8
        for (int j = 0; j < 64; j++) cnt += (cand[j] < mk);
        if (cnt < KLc) ssel[KAc + cnt] = (int)(mk & 0xFFFFFFFFull);
    }
    __syncthreads();

    if (tid < NNODES) g_sel[b * NNODES + tid] = ssel[tid];

    // ============ Phase C: gather nodes (transposed into Xs) ===============
    #pragma unroll 4
    for (int rw = 0; rw < NNODES; rw++) {
        int idx = ssel[rw];
        const float* src = (rw < KAc)
            ? (actor_feat + ((size_t)b * NAc + idx) * Dc)
            : (lane_feat  + ((size_t)b * NLc + idx) * Dc);
        Xs[tid * 36 + rw] = src[tid];
    }
    // NOTE: Xs writes are also ordered before GEMM1 reads by gemm_rc8's
    // stage-0 __syncthreads; the gather overlays on Hs were read above.

    // ============ Phase D: 2 layers of residual MLP + LayerNorm ============
    u64 acc[4][4];

    #pragma unroll 1
    for (int layer = 0; layer < 2; layer++) {
        const float* Wa  = layer ? W1a : W0a;
        const float* ba  = layer ? b1a : b0a;
        const float* Wb2 = layer ? W1b : W0b;
        const float* bb2 = layer ? b1b : b0b;

        // ---- GEMM1: H = gelu(X @ Wa + ba) -> Hs ----
        gemm_rc8(Xs, Wa, Wst, tid, rg, cg, acc);
        {
            float4 bq = *(const float4*)(ba + 4 * cg);
            float bar[4] = {bq.x, bq.y, bq.z, bq.w};
            #pragma unroll
            for (int rp = 0; rp < 4; rp++) {
                int r0 = 8 * rg + 2 * rp;
                #pragma unroll
                for (int c = 0; c < 4; c++) {
                    float lo, hi; unpk2(acc[rp][c], lo, hi);
                    lo = gelu_exact(lo + bar[c]);
                    hi = gelu_exact(hi + bar[c]);
                    *(float2*)(Hs + (4 * cg + c) * 36 + r0) = make_float2(lo, hi);
                }
            }
        }

        // ---- GEMM2: Y = H @ Wb + bb; Z = LN(X + Y) ----
        gemm_rc8(Hs, Wb2, Wst, tid, rg, cg, acc);
        {
            float4 bq = *(const float4*)(bb2 + 4 * cg);
            float bbr[4] = {bq.x, bq.y, bq.z, bq.w};
            float4 gq = *(const float4*)(gmm + 4 * cg);
            float4 pq = *(const float4*)(bta + 4 * cg);
            float gar[4] = {gq.x, gq.y, gq.z, gq.w};
            float per[4] = {pq.x, pq.y, pq.z, pq.w};

            #pragma unroll
            for (int rp = 0; rp < 4; rp++) {
                int r0 = 8 * rg + 2 * rp;
                float l0[4], l1[4];
                #pragma unroll
                for (int c = 0; c < 4; c++) {
                    float lo, hi; unpk2(acc[rp][c], lo, hi);
                    float2 xv = *(const float2*)(Xs + (4 * cg + c) * 36 + r0);
                    l0[c] = lo + bbr[c] + xv.x;
                    l1[c] = hi + bbr[c] + xv.y;
                }
                float m0 = wsum32(l0[0] + l0[1] + l0[2] + l0[3]) * 0.0078125f;
                float m1 = wsum32(l1[0] + l1[1] + l1[2] + l1[3]) * 0.0078125f;
                float q0 = 0.f, q1 = 0.f;
                #pragma unroll
                for (int c = 0; c < 4; c++) {
                    float d0 = l0[c] - m0; q0 += d0 * d0;
                    float d1 = l1[c] - m1; q1 += d1 * d1;
                }
                float i0 = rsqrtf(wsum32(q0) * 0.0078125f + 1e-5f);
                float i1 = rsqrtf(wsum32(q1) * 0.0078125f + 1e-5f);

                if (layer == 0) {
                    #pragma unroll
                    for (int c = 0; c < 4; c++) {
                        float z0 = (l0[c] - m0) * i0 * gar[c] + per[c];
                        float z1 = (l1[c] - m1) * i1 * gar[c] + per[c];
                        *(float2*)(Xs + (4 * cg + c) * 36 + r0) = make_float2(z0, z1);
                    }
                } else {
                    float4 o0, o1;
                    o0.x = (l0[0] - m0) * i0 * gar[0] + per[0];
                    o0.y = (l0[1] - m0) * i0 * gar[1] + per[1];
                    o0.z = (l0[2] - m0) * i0 * gar[2] + per[2];
                    o0.w = (l0[3] - m0) * i0 * gar[3] + per[3];
                    o1.x = (l1[0] - m1) * i1 * gar[0] + per[0];
                    o1.y = (l1[1] - m1) * i1 * gar[1] + per[1];
                    o1.z = (l1[2] - m1) * i1 * gar[2] + per[2];
                    o1.w = (l1[3] - m1) * i1 * gar[3] + per[3];
                    float* d0 = g_nodes + ((size_t)b * NNODES + r0) * Dc + 4 * cg;
                    *(float4*)d0        = o0;
                    *(float4*)(d0 + Dc) = o1;
                }
            }
        }
    }
}

// ---------------------------------------------------------------------------
// Scatter kernel: warp per row, float4 lanes (measured ~7us).
// ---------------------------------------------------------------------------
__global__ void __launch_bounds__(256)
scatter_kernel(float* __restrict__ out)
{
    __shared__ int ssel[NNODES];
    const int tid = threadIdx.x;
    const int b   = blockIdx.x;
    if (tid < NNODES) ssel[tid] = g_sel[b * NNODES + tid];
    __syncthreads();
    const int w = tid >> 5, lane = tid & 31;
    const size_t lane_base = (size_t)Bc * NAc * Dc;
    #pragma unroll
    for (int it = 0; it < 4; it++) {
        int rr = it * 8 + w;
        int idx = ssel[rr];
        size_t base = (rr < KAc)
            ? ((size_t)b * NAc + idx) * Dc
            : lane_base + ((size_t)b * NLc + idx) * Dc;
        ((float4*)(out + base))[lane] =
            ((const float4*)(g_nodes + ((size_t)b * NNODES + rr) * Dc))[lane];
    }
}

// ---------------------------------------------------------------------------
// kernel_launch: fork CE memcpys onto side stream (independent of compute),
// compute into scratch on main stream, join, scatter.
// ---------------------------------------------------------------------------
extern "C" void kernel_launch(void* const* d_in, const int* in_sizes, int n_in,
                              void* d_out, int out_size)
{
    const float* actor_feat   = (const float*)d_in[0];
    const float* lane_feat    = (const float*)d_in[1];
    const float* lane_centers = (const float*)d_in[2];
    const float* x_centers    = (const float*)d_in[3];
    const float* spike_rate   = (const float*)d_in[4];
    const void*  actor_valid  = d_in[5];
    const void*  lane_valid   = d_in[6];
    const float* W0a = (const float*)d_in[7];
    const float* b0a = (const float*)d_in[8];
    const float* W0b = (const float*)d_in[9];
    const float* b0b = (const float*)d_in[10];
    const float* W1a = (const float*)d_in[11];
    const float* b1a = (const float*)d_in[12];
    const float* W1b = (const float*)d_in[13];
    const float* b1b = (const float*)d_in[14];
    const float* gmm = (const float*)d_in[15];
    const float* bta = (const float*)d_in[16];
    float* out = (float*)d_out;

    const size_t actor_elems = (size_t)Bc * NAc * Dc;
    const size_t lane_elems  = (size_t)Bc * NLc * Dc;

    cudaFuncSetAttribute(compute_kernel,
                         cudaFuncAttributeMaxDynamicSharedMemorySize, SM_TOTAL);

    cudaStream_t s2;
    cudaEvent_t eA, eB;
    cudaStreamCreateWithFlags(&s2, cudaStreamNonBlocking);
    cudaEventCreateWithFlags(&eA, cudaEventDisableTiming);
    cudaEventCreateWithFlags(&eB, cudaEventDisableTiming);

    // Fork: CE copy of both pools into out.
    cudaEventRecord(eA, 0);
    cudaStreamWaitEvent(s2, eA, 0);
    cudaMemcpyAsync(out, actor_feat, actor_elems * sizeof(float),
                    cudaMemcpyDeviceToDevice, s2);
    cudaMemcpyAsync(out + actor_elems, lane_feat, lane_elems * sizeof(float),
                    cudaMemcpyDeviceToDevice, s2);
    cudaEventRecord(eB, s2);

    // Main stream: tournament select + MLP into scratch.
    compute_kernel<<<Bc, 128, SM_TOTAL>>>(actor_feat, lane_feat, lane_centers,
                                          x_centers, spike_rate, actor_valid,
                                          lane_valid,
                                          W0a, b0a, W0b, b0b,
                                          W1a, b1a, W1b, b1b,
                                          gmm, bta);

    // Join, then overwrite the 32 selected rows per batch.
    cudaStreamWaitEvent(0, eB, 0);
    scatter_kernel<<<Bc, 256>>>(out);
}